// round 1
// baseline (speedup 1.0000x reference)
#include <cuda_runtime.h>
#include <cuda_bf16.h>

// MahalanobisLoss2D: out = mean_b( (d_b^T P d_b) / n_b ),
//   d_b = (y_true_b - y_pred_b) masked to t < n_b
//   P = I + coef*(super+sub), coef = -p/(1+p^2), p = 2*sigmoid(param)-1
// => quad_b = s0_b + 2*coef*s1_b, s0 = sum d_t^2, s1 = sum d_t d_{t+1}
//
// Inputs (metadata order): y_true f32[B*64], y_pred f32[B*64], param f32[1], n i32[B]

#define D 64
#define ROWS_PER_BLOCK 64   // 8 warps * 8 rows
#define THREADS 256
#define NSLOTS 1024

__device__ double g_acc0[NSLOTS];
__device__ double g_acc1[NSLOTS];

__global__ void mahal_init_kernel() {
    int i = blockIdx.x * blockDim.x + threadIdx.x;
    if (i < NSLOTS) { g_acc0[i] = 0.0; g_acc1[i] = 0.0; }
}

__global__ __launch_bounds__(THREADS)
void mahal_main_kernel(const float* __restrict__ yt,
                       const float* __restrict__ yp,
                       const int*  __restrict__ nv,
                       int B) {
    const int warp = threadIdx.x >> 5;
    const int lane = threadIdx.x & 31;
    const int half = lane >> 4;       // which of the warp's 2 rows
    const int q    = lane & 15;       // float4 index within row (16 * 4 = 64)

    const int rowBase = blockIdx.x * ROWS_PER_BLOCK + warp * 8;

    float acc0 = 0.0f, acc1 = 0.0f;

    #pragma unroll
    for (int it = 0; it < 4; ++it) {
        const int row = rowBase + it * 2 + half;

        float d0 = 0.f, d1 = 0.f, d2 = 0.f, d3 = 0.f;
        float inv = 0.f;
        if (row < B) {
            const float4 t4 = reinterpret_cast<const float4*>(yt)[row * (D/4) + q];
            const float4 p4 = reinterpret_cast<const float4*>(yp)[row * (D/4) + q];
            const int nr = nv[row];
            const int t0 = q * 4;
            d0 = (t0 + 0 < nr) ? (t4.x - p4.x) : 0.f;
            d1 = (t0 + 1 < nr) ? (t4.y - p4.y) : 0.f;
            d2 = (t0 + 2 < nr) ? (t4.z - p4.z) : 0.f;
            d3 = (t0 + 3 < nr) ? (t4.w - p4.w) : 0.f;
            inv = 1.0f / (float)nr;
        }

        // neighbor lane's first masked diff (for the t=4q+3 -> 4q+4 cross term)
        const float nb = __shfl_down_sync(0xffffffffu, d0, 1);

        float s0 = d0 * d0 + d1 * d1 + d2 * d2 + d3 * d3;
        float s1 = d0 * d1 + d1 * d2 + d2 * d3;
        if (q != 15) s1 += d3 * nb;   // lane 15 is the row's last quad: no neighbor term

        acc0 += s0 * inv;
        acc1 += s1 * inv;
    }

    // full-warp reduction (rows mix: only the global sum matters)
    #pragma unroll
    for (int o = 16; o > 0; o >>= 1) {
        acc0 += __shfl_xor_sync(0xffffffffu, acc0, o);
        acc1 += __shfl_xor_sync(0xffffffffu, acc1, o);
    }

    __shared__ float sh0[8], sh1[8];
    if (lane == 0) { sh0[warp] = acc0; sh1[warp] = acc1; }
    __syncthreads();

    if (threadIdx.x == 0) {
        float b0 = 0.f, b1 = 0.f;
        #pragma unroll
        for (int i = 0; i < 8; ++i) { b0 += sh0[i]; b1 += sh1[i]; }
        const int slot = blockIdx.x & (NSLOTS - 1);
        atomicAdd(&g_acc0[slot], (double)b0);
        atomicAdd(&g_acc1[slot], (double)b1);
    }
}

__global__ void mahal_finalize_kernel(const float* __restrict__ param,
                                      float* __restrict__ out,
                                      double invB) {
    __shared__ double s0s[256], s1s[256];
    const int t = threadIdx.x;
    double a0 = 0.0, a1 = 0.0;
    for (int i = t; i < NSLOTS; i += 256) { a0 += g_acc0[i]; a1 += g_acc1[i]; }
    s0s[t] = a0; s1s[t] = a1;
    __syncthreads();
    for (int s = 128; s > 0; s >>= 1) {
        if (t < s) { s0s[t] += s0s[t + s]; s1s[t] += s1s[t + s]; }
        __syncthreads();
    }
    if (t == 0) {
        const float pm = param[0];
        // p = 2*sigmoid(pm) - 1
        const double p = 2.0 / (1.0 + exp((double)(-pm))) - 1.0;
        const double coef = -p / (1.0 + p * p);
        *out = (float)((s0s[0] + 2.0 * coef * s1s[0]) * invB);
    }
}

extern "C" void kernel_launch(void* const* d_in, const int* in_sizes, int n_in,
                              void* d_out, int out_size) {
    const float* y_true = (const float*)d_in[0];
    const float* y_pred = (const float*)d_in[1];
    const float* param  = (const float*)d_in[2];
    const int*   nvec   = (const int*)  d_in[3];
    float* out = (float*)d_out;

    const int B = in_sizes[3];
    const int blocks = (B + ROWS_PER_BLOCK - 1) / ROWS_PER_BLOCK;

    mahal_init_kernel<<<1, NSLOTS>>>();
    mahal_main_kernel<<<blocks, THREADS>>>(y_true, y_pred, nvec, B);
    mahal_finalize_kernel<<<1, 256>>>(param, out, 1.0 / (double)B);
}

// round 2
// speedup vs baseline: 1.1648x; 1.1648x over previous
#include <cuda_runtime.h>
#include <cuda_bf16.h>

// MahalanobisLoss2D: out = mean_b( (d_b^T P d_b) / n_b ),
//   d_b = (y_true_b - y_pred_b) masked to t < n_b
//   P = I + coef*(super+sub), coef = -p/(1+p^2), p = 2*sigmoid(param)-1
// => quad_b = s0_b + 2*coef*s1_b, s0 = sum d_t^2, s1 = sum d_t d_{t+1}
//
// Single-kernel: partial sums -> slotted double atomics -> last block finalizes
// and self-resets all global state (so graph replays are deterministic).
//
// Inputs (metadata order): y_true f32[B*64], y_pred f32[B*64], param f32[1], n i32[B]

#define D 64
#define ROWS_PER_BLOCK 64   // 8 warps * 8 rows
#define THREADS 256
#define NSLOTS 1024

__device__ double       g_acc0[NSLOTS];   // zero at module load; re-zeroed by last block
__device__ double       g_acc1[NSLOTS];
__device__ unsigned int g_ticket;         // zero at module load; reset by last block

__global__ __launch_bounds__(THREADS)
void mahal_fused_kernel(const float* __restrict__ yt,
                        const float* __restrict__ yp,
                        const int*  __restrict__ nv,
                        const float* __restrict__ param,
                        float* __restrict__ out,
                        int B, int nblocks, double invB) {
    const int warp = threadIdx.x >> 5;
    const int lane = threadIdx.x & 31;
    const int half = lane >> 4;       // which of the warp's 2 rows
    const int q    = lane & 15;       // float4 index within row (16 * 4 = 64)

    const int rowBase = blockIdx.x * ROWS_PER_BLOCK + warp * 8;

    float acc0 = 0.0f, acc1 = 0.0f;

    if (rowBase + 7 < B) {
        // ---- fast path: all 8 rows valid, loads unpredicated (front-batched) ----
        float4 t4v[4], p4v[4];
        int    nr[4];
        #pragma unroll
        for (int it = 0; it < 4; ++it) {
            const int row = rowBase + it * 2 + half;
            t4v[it] = reinterpret_cast<const float4*>(yt)[row * (D/4) + q];
            p4v[it] = reinterpret_cast<const float4*>(yp)[row * (D/4) + q];
            nr[it]  = nv[row];
        }
        #pragma unroll
        for (int it = 0; it < 4; ++it) {
            const int t0 = q * 4;
            const float d0 = (t0 + 0 < nr[it]) ? (t4v[it].x - p4v[it].x) : 0.f;
            const float d1 = (t0 + 1 < nr[it]) ? (t4v[it].y - p4v[it].y) : 0.f;
            const float d2 = (t0 + 2 < nr[it]) ? (t4v[it].z - p4v[it].z) : 0.f;
            const float d3 = (t0 + 3 < nr[it]) ? (t4v[it].w - p4v[it].w) : 0.f;
            const float inv = 1.0f / (float)nr[it];

            const float nb = __shfl_down_sync(0xffffffffu, d0, 1);

            float s0 = d0 * d0 + d1 * d1 + d2 * d2 + d3 * d3;
            float s1 = d0 * d1 + d1 * d2 + d2 * d3;
            if (q != 15) s1 += d3 * nb;

            acc0 += s0 * inv;
            acc1 += s1 * inv;
        }
    } else {
        // ---- tail path: per-row guard ----
        #pragma unroll
        for (int it = 0; it < 4; ++it) {
            const int row = rowBase + it * 2 + half;
            float d0 = 0.f, d1 = 0.f, d2 = 0.f, d3 = 0.f;
            float inv = 0.f;
            if (row < B) {
                const float4 t4 = reinterpret_cast<const float4*>(yt)[row * (D/4) + q];
                const float4 p4 = reinterpret_cast<const float4*>(yp)[row * (D/4) + q];
                const int nrr = nv[row];
                const int t0 = q * 4;
                d0 = (t0 + 0 < nrr) ? (t4.x - p4.x) : 0.f;
                d1 = (t0 + 1 < nrr) ? (t4.y - p4.y) : 0.f;
                d2 = (t0 + 2 < nrr) ? (t4.z - p4.z) : 0.f;
                d3 = (t0 + 3 < nrr) ? (t4.w - p4.w) : 0.f;
                inv = 1.0f / (float)nrr;
            }
            const float nb = __shfl_down_sync(0xffffffffu, d0, 1);
            float s0 = d0 * d0 + d1 * d1 + d2 * d2 + d3 * d3;
            float s1 = d0 * d1 + d1 * d2 + d2 * d3;
            if (q != 15) s1 += d3 * nb;
            acc0 += s0 * inv;
            acc1 += s1 * inv;
        }
    }

    // full-warp reduction (rows mix: only the global sum matters)
    #pragma unroll
    for (int o = 16; o > 0; o >>= 1) {
        acc0 += __shfl_xor_sync(0xffffffffu, acc0, o);
        acc1 += __shfl_xor_sync(0xffffffffu, acc1, o);
    }

    __shared__ float sh0[8], sh1[8];
    if (lane == 0) { sh0[warp] = acc0; sh1[warp] = acc1; }
    __syncthreads();

    __shared__ bool amLast;
    if (threadIdx.x == 0) {
        float b0 = 0.f, b1 = 0.f;
        #pragma unroll
        for (int i = 0; i < 8; ++i) { b0 += sh0[i]; b1 += sh1[i]; }
        const int slot = blockIdx.x & (NSLOTS - 1);
        atomicAdd(&g_acc0[slot], (double)b0);
        atomicAdd(&g_acc1[slot], (double)b1);
        __threadfence();
        const unsigned int ticket = atomicAdd(&g_ticket, 1u);
        amLast = (ticket == (unsigned int)(nblocks - 1));
    }
    __syncthreads();

    if (amLast) {
        // ---- finalize: reduce slots, compute scalar epilogue, reset state ----
        __shared__ double s0s[THREADS], s1s[THREADS];
        const int t = threadIdx.x;
        double a0 = 0.0, a1 = 0.0;
        for (int i = t; i < NSLOTS; i += THREADS) {
            a0 += g_acc0[i]; g_acc0[i] = 0.0;
            a1 += g_acc1[i]; g_acc1[i] = 0.0;
        }
        s0s[t] = a0; s1s[t] = a1;
        __syncthreads();
        for (int s = THREADS / 2; s > 0; s >>= 1) {
            if (t < s) { s0s[t] += s0s[t + s]; s1s[t] += s1s[t + s]; }
            __syncthreads();
        }
        if (t == 0) {
            const float pm = param[0];
            const double p = 2.0 / (1.0 + exp((double)(-pm))) - 1.0;   // 2*sigmoid - 1
            const double coef = -p / (1.0 + p * p);
            *out = (float)((s0s[0] + 2.0 * coef * s1s[0]) * invB);
            g_ticket = 0u;                 // reset for next graph replay
            __threadfence();
        }
    }
}

extern "C" void kernel_launch(void* const* d_in, const int* in_sizes, int n_in,
                              void* d_out, int out_size) {
    const float* y_true = (const float*)d_in[0];
    const float* y_pred = (const float*)d_in[1];
    const float* param  = (const float*)d_in[2];
    const int*   nvec   = (const int*)  d_in[3];
    float* out = (float*)d_out;

    const int B = in_sizes[3];
    const int blocks = (B + ROWS_PER_BLOCK - 1) / ROWS_PER_BLOCK;

    mahal_fused_kernel<<<blocks, THREADS>>>(y_true, y_pred, nvec, param, out,
                                            B, blocks, 1.0 / (double)B);
}